// round 13
// baseline (speedup 1.0000x reference)
#include <cuda_runtime.h>
#include <math.h>

#define NSEG 1024
#define NPIX (512 * 512)
#define NCH  21
#define NB   4
#define HB   128           // K1 x-blocks per batch (512 blocks total = 1 wave)
#define QXR  128           // K3 blocks per batch (8 rows each) -> 512 blocks
#define K1_TOTAL (HB * NB)
#define K3_TOTAL (QXR * NB)

// Persistent state: starts zero (static init); each stage's last block
// restores what the next replay needs (graph-replay safe).
__device__ float  g_msum[NB * NSEG];   // atomics in K1; zeroed by K1 last block
__device__ float  g_mcnt[NB * NSEG];   // atomics in K1; zeroed by K1 last block
__device__ float  g_m[NB * NSEG];      // overwritten by K1 last block
__device__ double g_w2[NB];            // atomics in K1; zeroed by K3 last block
__device__ double g_quadp[K3_TOTAL];   // per-block partials — overwritten
__device__ unsigned int g_done1;       // K1 counter; reset by K1 last block
__device__ unsigned int g_done3;       // K3 counter; reset by K3 last block

// ---------------------------------------------------------------------------
// K1: grid (HB, NB) x 512 — one wave. Shared-mem histogram over 2048 px +
// 2048-float4 slice of ||W||^2. Flush via global atomics. The LAST block
// (completion counter) computes g_m = msum/mcnt and zeroes msum/mcnt.
// ---------------------------------------------------------------------------
__global__ __launch_bounds__(512) void k1(const float* __restrict__ pred,
                                          const void* __restrict__ ids_v,
                                          const float* __restrict__ W) {
    __shared__ float s_sum[NSEG];
    __shared__ int   s_cnt[NSEG];
    __shared__ int   s_nonzero;
    __shared__ float red[16];
    __shared__ int   s_last;

    const int tid = threadIdx.x;
    const int b   = blockIdx.y;
    const int x   = blockIdx.x;

    if (tid == 0) s_nonzero = 0;
    for (int i = tid; i < NSEG; i += 512) { s_sum[i] = 0.f; s_cnt[i] = 0; }
    __syncthreads();

    // dtype probe: int64 ids in [0,1024) -> all odd 32-bit words zero (L2-hot).
    if (tid < 128 && ((const unsigned int*)ids_v)[2 * tid + 1] != 0u)
        atomicOr(&s_nonzero, 1);
    __syncthreads();
    const int is64 = !s_nonzero;

    // ---- histogram phase ----
    const float4* __restrict__ p4 =
        (const float4*)(pred + (size_t)b * NCH * NPIX);
    const int4* __restrict__ id32v =
        (const int4*)((const int*)ids_v + (size_t)b * NPIX);
    const longlong2* __restrict__ id64v =
        (const longlong2*)((const long long*)ids_v + (size_t)b * NPIX);

    const int q = x * 512 + tid;                     // one float4-group/thread
    float4 acc = make_float4(0.f, 0.f, 0.f, 0.f);
    #pragma unroll
    for (int c = 0; c < NCH; ++c) {
        float4 v = p4[(size_t)c * (NPIX / 4) + q];
        acc.x += v.x; acc.y += v.y; acc.z += v.z; acc.w += v.w;
    }
    int i0, i1, i2, i3;
    if (is64) {
        longlong2 a = id64v[2 * q];
        longlong2 c = id64v[2 * q + 1];
        i0 = (int)a.x; i1 = (int)a.y; i2 = (int)c.x; i3 = (int)c.y;
    } else {
        int4 iv = id32v[q];
        i0 = iv.x; i1 = iv.y; i2 = iv.z; i3 = iv.w;
    }
    atomicAdd(&s_sum[i0 & (NSEG - 1)], acc.x); atomicAdd(&s_cnt[i0 & (NSEG - 1)], 1);
    atomicAdd(&s_sum[i1 & (NSEG - 1)], acc.y); atomicAdd(&s_cnt[i1 & (NSEG - 1)], 1);
    atomicAdd(&s_sum[i2 & (NSEG - 1)], acc.z); atomicAdd(&s_cnt[i2 & (NSEG - 1)], 1);
    atomicAdd(&s_sum[i3 & (NSEG - 1)], acc.w); atomicAdd(&s_cnt[i3 & (NSEG - 1)], 1);

    // ---- W^2 phase ----
    const float4* __restrict__ Wb = (const float4*)(W + (size_t)b * NSEG * NSEG);
    float ws = 0.f;
    #pragma unroll
    for (int j = 0; j < 4; ++j) {
        float4 v = Wb[x * 2048 + j * 512 + tid];
        ws += v.x * v.x + v.y * v.y + v.z * v.z + v.w * v.w;
    }
    #pragma unroll
    for (int o = 16; o > 0; o >>= 1)
        ws += __shfl_xor_sync(0xffffffffu, ws, o);
    if ((tid & 31) == 0) red[tid >> 5] = ws;

    __syncthreads();

    // ---- flush ----
    for (int i = tid; i < NSEG; i += 512) {
        int c = s_cnt[i];
        if (c != 0) {
            atomicAdd(&g_msum[b * NSEG + i], s_sum[i]);
            atomicAdd(&g_mcnt[b * NSEG + i], (float)c);
        }
    }
    if (tid == 0) {
        double t = 0.0;
        #pragma unroll
        for (int w = 0; w < 16; ++w) t += (double)red[w];
        atomicAdd(&g_w2[b], t);

        __threadfence();
        unsigned int prev = atomicAdd(&g_done1, 1u);
        s_last = (prev == K1_TOTAL - 1);
    }
    __syncthreads();

    // ---- last block: compute g_m once, zero msum/mcnt for next replay ----
    if (s_last) {
        __threadfence();
        for (int i = tid; i < NB * NSEG; i += 512) {
            float c = g_mcnt[i];
            g_m[i] = (c > 0.f) ? g_msum[i] / c : 0.f;
            g_msum[i] = 0.f;
            g_mcnt[i] = 0.f;
        }
        if (tid == 0) g_done1 = 0u;
    }
}

// ---------------------------------------------------------------------------
// K3: quad[b] = m^T L m. 512 blocks x 256 thr, __launch_bounds__(256,4)
// => 64 regs/thread. One warp per FULL row: 8 float4 loads in two explicit
// batches of 4 (high MLP). Block partial -> g_quadp slot. Last block reduces,
// writes loss, resets w2/done state.
// ---------------------------------------------------------------------------
__global__ __launch_bounds__(256, 4) void k3(const float* __restrict__ L,
                                             float* __restrict__ out) {
    __shared__ float  s_m[NSEG];
    __shared__ double qred[8];
    __shared__ int    s_last;

    const int blk  = blockIdx.x;                     // 0..511
    const int b    = blk >> 7;                       // batch
    const int xr   = blk & (QXR - 1);                // row-group within batch
    const int tid  = threadIdx.x;
    const int warp = tid >> 5;
    const int lane = tid & 31;

    for (int i = tid; i < NSEG; i += 256)
        s_m[i] = g_m[b * NSEG + i];
    __syncthreads();

    const int r = xr * 8 + warp;                     // full row per warp
    const float4* __restrict__ Lr =
        (const float4*)(L + (size_t)b * NSEG * NSEG + (size_t)r * NSEG);
    const float4* __restrict__ sm4 = (const float4*)s_m;

    // batch A: 4 independent float4 loads
    float4 l0 = Lr[lane];
    float4 l1 = Lr[32 + lane];
    float4 l2 = Lr[64 + lane];
    float4 l3 = Lr[96 + lane];
    float4 m0 = sm4[lane];
    float4 m1 = sm4[32 + lane];
    float4 m2 = sm4[64 + lane];
    float4 m3 = sm4[96 + lane];
    float sA = l0.x * m0.x + l0.y * m0.y + l0.z * m0.z + l0.w * m0.w;
    float sB = l1.x * m1.x + l1.y * m1.y + l1.z * m1.z + l1.w * m1.w;
    sA += l2.x * m2.x + l2.y * m2.y + l2.z * m2.z + l2.w * m2.w;
    sB += l3.x * m3.x + l3.y * m3.y + l3.z * m3.z + l3.w * m3.w;

    // batch B: next 4 independent float4 loads
    l0 = Lr[128 + lane];
    l1 = Lr[160 + lane];
    l2 = Lr[192 + lane];
    l3 = Lr[224 + lane];
    m0 = sm4[128 + lane];
    m1 = sm4[160 + lane];
    m2 = sm4[192 + lane];
    m3 = sm4[224 + lane];
    sA += l0.x * m0.x + l0.y * m0.y + l0.z * m0.z + l0.w * m0.w;
    sB += l1.x * m1.x + l1.y * m1.y + l1.z * m1.z + l1.w * m1.w;
    sA += l2.x * m2.x + l2.y * m2.y + l2.z * m2.z + l2.w * m2.w;
    sB += l3.x * m3.x + l3.y * m3.y + l3.z * m3.z + l3.w * m3.w;

    float s = sA + sB;
    #pragma unroll
    for (int o = 16; o > 0; o >>= 1)
        s += __shfl_xor_sync(0xffffffffu, s, o);
    if (lane == 0)
        qred[warp] = (double)s * (double)s_m[r];
    __syncthreads();

    if (tid == 0) {
        double t = 0.0;
        #pragma unroll
        for (int w = 0; w < 8; ++w) t += qred[w];
        g_quadp[blk] = t;                            // overwrite, no atomic

        __threadfence();
        unsigned int prev = atomicAdd(&g_done3, 1u);
        s_last = (prev == K3_TOTAL - 1);
    }
    __syncthreads();

    if (s_last) {
        __threadfence();
        // warps 0..NB-1 reduce each batch's QXR partials (contiguous slots)
        if (warp < NB) {
            double t = 0.0;
            #pragma unroll
            for (int j = 0; j < QXR / 32; ++j)       // 4 loads
                t += g_quadp[warp * QXR + j * 32 + lane];
            #pragma unroll
            for (int o = 16; o > 0; o >>= 1)
                t += __shfl_xor_sync(0xffffffffu, t, o);
            if (lane == 0) qred[warp] = t;
        }
        __syncthreads();
        if (tid == 0) {
            double loss = 0.0;
            #pragma unroll
            for (int k = 0; k < NB; ++k)
                loss += (2.0 / sqrt(g_w2[k])) * ((double)NCH * qred[k]);
            out[0] = (float)loss;
            __threadfence();
            #pragma unroll
            for (int k = 0; k < NB; ++k) g_w2[k] = 0.0;
            g_done3 = 0u;
        }
    }
}

extern "C" void kernel_launch(void* const* d_in, const int* in_sizes, int n_in,
                              void* d_out, int out_size) {
    const float* pred = (const float*)d_in[0];
    const float* W    = (const float*)d_in[1];
    const float* L    = (const float*)d_in[2];
    const void*  ids  = (const void*)d_in[3];
    float* out = (float*)d_out;

    k1<<<dim3(HB, NB), 512>>>(pred, ids, W);
    k3<<<K3_TOTAL, 256>>>(L, out);
}

// round 14
// speedup vs baseline: 1.0741x; 1.0741x over previous
#include <cuda_runtime.h>
#include <math.h>

#define NSEG 1024
#define NPIX (512 * 512)
#define NCH  21
#define NB   4
#define HB   128                 // x-blocks per batch
#define TOTAL (HB * NB)          // 512 blocks — all co-resident (4/SM x 148)

// Persistent state: starts zero (static init); the final block resets
// everything it used, so each graph replay sees clean state.
__device__ float  g_msum[NB * NSEG];
__device__ float  g_mcnt[NB * NSEG];
__device__ double g_w2[NB];
__device__ double g_quadp[TOTAL];
__device__ unsigned int g_bar_cnt;
__device__ int          g_bar_flag;
__device__ unsigned int g_done;

// ---------------------------------------------------------------------------
// Single fused kernel. grid (HB, NB) x 512, launch_bounds(512,4) so all 512
// blocks are resident in one wave (spin barrier is deadlock-free).
//   Phase 1: shared-mem histogram (2048 px) + ||W||^2 slice; atomic flush.
//   Device-wide barrier (counter + flag spin, tid0 only).
//   Phase 2: m = msum/mcnt (local, L2-hot), 8 rows of m^T L m per block.
//   Last block: reduce partials, write loss, reset all state.
// ---------------------------------------------------------------------------
__global__ __launch_bounds__(512, 4) void kfused(const float* __restrict__ pred,
                                                 const void* __restrict__ ids_v,
                                                 const float* __restrict__ W,
                                                 const float* __restrict__ L,
                                                 float* __restrict__ out) {
    __shared__ float  s_mf[NSEG];       // phase1: hist sums; phase2: m
    __shared__ int    s_cnt[NSEG];
    __shared__ int    s_nonzero;
    __shared__ float  red[16];
    __shared__ double qsh[16];
    __shared__ int    s_last;

    const int tid = threadIdx.x;
    const int b   = blockIdx.y;
    const int x   = blockIdx.x;

    // ================= Phase 1: histogram + W^2 =================
    if (tid == 0) s_nonzero = 0;
    for (int i = tid; i < NSEG; i += 512) { s_mf[i] = 0.f; s_cnt[i] = 0; }
    __syncthreads();

    // dtype probe: int64 ids in [0,1024) -> all odd 32-bit words zero.
    if (tid < 128 && ((const unsigned int*)ids_v)[2 * tid + 1] != 0u)
        atomicOr(&s_nonzero, 1);
    __syncthreads();
    const int is64 = !s_nonzero;

    const float4* __restrict__ p4 =
        (const float4*)(pred + (size_t)b * NCH * NPIX);
    const int4* __restrict__ id32v =
        (const int4*)((const int*)ids_v + (size_t)b * NPIX);
    const longlong2* __restrict__ id64v =
        (const longlong2*)((const long long*)ids_v + (size_t)b * NPIX);

    const int q = x * 512 + tid;                     // one float4-group/thread
    float4 acc = make_float4(0.f, 0.f, 0.f, 0.f);
    #pragma unroll
    for (int c = 0; c < NCH; ++c) {
        float4 v = p4[(size_t)c * (NPIX / 4) + q];
        acc.x += v.x; acc.y += v.y; acc.z += v.z; acc.w += v.w;
    }
    int i0, i1, i2, i3;
    if (is64) {
        longlong2 a = id64v[2 * q];
        longlong2 c = id64v[2 * q + 1];
        i0 = (int)a.x; i1 = (int)a.y; i2 = (int)c.x; i3 = (int)c.y;
    } else {
        int4 iv = id32v[q];
        i0 = iv.x; i1 = iv.y; i2 = iv.z; i3 = iv.w;
    }
    atomicAdd(&s_mf[i0 & (NSEG - 1)], acc.x); atomicAdd(&s_cnt[i0 & (NSEG - 1)], 1);
    atomicAdd(&s_mf[i1 & (NSEG - 1)], acc.y); atomicAdd(&s_cnt[i1 & (NSEG - 1)], 1);
    atomicAdd(&s_mf[i2 & (NSEG - 1)], acc.z); atomicAdd(&s_cnt[i2 & (NSEG - 1)], 1);
    atomicAdd(&s_mf[i3 & (NSEG - 1)], acc.w); atomicAdd(&s_cnt[i3 & (NSEG - 1)], 1);

    // W^2 slice
    const float4* __restrict__ Wb = (const float4*)(W + (size_t)b * NSEG * NSEG);
    float ws = 0.f;
    #pragma unroll
    for (int j = 0; j < 4; ++j) {
        float4 v = Wb[x * 2048 + j * 512 + tid];
        ws += v.x * v.x + v.y * v.y + v.z * v.z + v.w * v.w;
    }
    #pragma unroll
    for (int o = 16; o > 0; o >>= 1)
        ws += __shfl_xor_sync(0xffffffffu, ws, o);
    if ((tid & 31) == 0) red[tid >> 5] = ws;

    __syncthreads();

    // flush
    for (int i = tid; i < NSEG; i += 512) {
        int c = s_cnt[i];
        if (c != 0) {
            atomicAdd(&g_msum[b * NSEG + i], s_mf[i]);
            atomicAdd(&g_mcnt[b * NSEG + i], (float)c);
        }
    }
    if (tid == 0) {
        double t = 0.0;
        #pragma unroll
        for (int w = 0; w < 16; ++w) t += (double)red[w];
        atomicAdd(&g_w2[b], t);
    }

    // ================= Device-wide barrier =================
    __threadfence();
    __syncthreads();
    if (tid == 0) {
        unsigned int p = atomicAdd(&g_bar_cnt, 1u);
        if (p == TOTAL - 1) {
            atomicExch(&g_bar_flag, 1);              // release
        } else {
            while (atomicAdd(&g_bar_flag, 0) == 0) __nanosleep(64);
        }
        __threadfence();                             // acquire
    }
    __syncthreads();

    // ================= Phase 2: m + quad rows =================
    for (int i = tid; i < NSEG; i += 512) {
        float c = g_mcnt[b * NSEG + i];
        s_mf[i] = (c > 0.f) ? g_msum[b * NSEG + i] / c : 0.f;
    }
    __syncthreads();

    const int warp = tid >> 5;                       // 0..15
    const int lane = tid & 31;
    const int r    = x * 8 + (warp >> 1);            // 8 rows per block
    const int half = warp & 1;                       // half-row per warp (2KB)
    const float4* __restrict__ Lr =
        (const float4*)(L + (size_t)b * NSEG * NSEG + (size_t)r * NSEG);
    const float4* __restrict__ sm4 = (const float4*)s_mf;

    const int base = half * 128 + lane;
    // 4 independent float4 loads (batched for MLP)
    float4 l0 = Lr[base];
    float4 l1 = Lr[base + 32];
    float4 l2 = Lr[base + 64];
    float4 l3 = Lr[base + 96];
    float4 m0 = sm4[base];
    float4 m1 = sm4[base + 32];
    float4 m2 = sm4[base + 64];
    float4 m3 = sm4[base + 96];
    float s = l0.x * m0.x + l0.y * m0.y + l0.z * m0.z + l0.w * m0.w;
    s += l1.x * m1.x + l1.y * m1.y + l1.z * m1.z + l1.w * m1.w;
    s += l2.x * m2.x + l2.y * m2.y + l2.z * m2.z + l2.w * m2.w;
    s += l3.x * m3.x + l3.y * m3.y + l3.z * m3.z + l3.w * m3.w;

    #pragma unroll
    for (int o = 16; o > 0; o >>= 1)
        s += __shfl_xor_sync(0xffffffffu, s, o);
    if (lane == 0) qsh[warp] = (double)s;
    __syncthreads();

    if (tid == 0) {
        double qv = 0.0;
        #pragma unroll
        for (int t = 0; t < 8; ++t)
            qv += (qsh[2 * t] + qsh[2 * t + 1]) * (double)s_mf[x * 8 + t];
        g_quadp[b * HB + x] = qv;

        __threadfence();
        unsigned int p = atomicAdd(&g_done, 1u);
        s_last = (p == TOTAL - 1);
    }
    __syncthreads();

    // ================= Final block: reduce + output + reset =================
    if (s_last) {
        __threadfence();
        if (warp < NB) {                             // warps 0..3: one batch each
            double t = 0.0;
            #pragma unroll
            for (int j = 0; j < HB / 32; ++j)        // 4 loads
                t += g_quadp[warp * HB + j * 32 + lane];
            #pragma unroll
            for (int o = 16; o > 0; o >>= 1)
                t += __shfl_xor_sync(0xffffffffu, t, o);
            if (lane == 0) qsh[warp] = t;
        }
        __syncthreads();
        if (tid == 0) {
            double loss = 0.0;
            #pragma unroll
            for (int k = 0; k < NB; ++k)
                loss += (2.0 / sqrt(g_w2[k])) * ((double)NCH * qsh[k]);
            out[0] = (float)loss;
            __threadfence();
            #pragma unroll
            for (int k = 0; k < NB; ++k) g_w2[k] = 0.0;
            g_bar_cnt  = 0u;
            g_bar_flag = 0;
            g_done     = 0u;
        }
        // reset histogram accumulators for the next graph replay
        for (int i = tid; i < NB * NSEG; i += 512) {
            g_msum[i] = 0.f;
            g_mcnt[i] = 0.f;
        }
    }
}

extern "C" void kernel_launch(void* const* d_in, const int* in_sizes, int n_in,
                              void* d_out, int out_size) {
    const float* pred = (const float*)d_in[0];
    const float* W    = (const float*)d_in[1];
    const float* L    = (const float*)d_in[2];
    const void*  ids  = (const void*)d_in[3];
    float* out = (float*)d_out;

    kfused<<<dim3(HB, NB), 512>>>(pred, ids, W, L, out);
}

// round 15
// speedup vs baseline: 1.1159x; 1.0389x over previous
#include <cuda_runtime.h>
#include <math.h>

#define NSEG 1024
#define NPIX (512 * 512)
#define NCH  21
#define NB   4
#define HB   128           // K1 x-blocks per batch (512 blocks total = 1 wave)
#define QB   128           // K3 blocks per batch -> 512 blocks
#define K3_TOTAL (QB * NB)

// Persistent state: starts zero (static init); K3's last block restores
// everything for the next graph replay.
__device__ float  g_msum[NB * NSEG];   // atomics in K1; zeroed by K3 last block
__device__ float  g_mcnt[NB * NSEG];   // atomics in K1; zeroed by K3 last block
__device__ double g_w2[NB];            // atomics in K1; zeroed by K3 last block
__device__ double g_quadp[K3_TOTAL];   // per-block partials — overwritten
__device__ unsigned int g_done;        // K3 counter; reset by K3 last block

// ---------------------------------------------------------------------------
// K1: grid (HB, NB) x 512 — one wave. Shared-mem histogram over 2048 px +
// 2048-float4 slice of ||W||^2. Flush via global atomics (skip empty bins).
// (Same as R12 best — 67% DRAM.)
// ---------------------------------------------------------------------------
__global__ __launch_bounds__(512) void k1(const float* __restrict__ pred,
                                          const void* __restrict__ ids_v,
                                          const float* __restrict__ W) {
    __shared__ float s_sum[NSEG];
    __shared__ int   s_cnt[NSEG];
    __shared__ int   s_nonzero;
    __shared__ float red[16];

    const int tid = threadIdx.x;
    const int b   = blockIdx.y;
    const int x   = blockIdx.x;

    if (tid == 0) s_nonzero = 0;
    for (int i = tid; i < NSEG; i += 512) { s_sum[i] = 0.f; s_cnt[i] = 0; }
    __syncthreads();

    // dtype probe: int64 ids in [0,1024) -> all odd 32-bit words zero (L2-hot).
    if (tid < 128 && ((const unsigned int*)ids_v)[2 * tid + 1] != 0u)
        atomicOr(&s_nonzero, 1);
    __syncthreads();
    const int is64 = !s_nonzero;

    // ---- histogram phase ----
    const float4* __restrict__ p4 =
        (const float4*)(pred + (size_t)b * NCH * NPIX);
    const int4* __restrict__ id32v =
        (const int4*)((const int*)ids_v + (size_t)b * NPIX);
    const longlong2* __restrict__ id64v =
        (const longlong2*)((const long long*)ids_v + (size_t)b * NPIX);

    const int q = x * 512 + tid;                     // one float4-group/thread
    float4 acc = make_float4(0.f, 0.f, 0.f, 0.f);
    #pragma unroll
    for (int c = 0; c < NCH; ++c) {
        float4 v = p4[(size_t)c * (NPIX / 4) + q];
        acc.x += v.x; acc.y += v.y; acc.z += v.z; acc.w += v.w;
    }
    int i0, i1, i2, i3;
    if (is64) {
        longlong2 a = id64v[2 * q];
        longlong2 c = id64v[2 * q + 1];
        i0 = (int)a.x; i1 = (int)a.y; i2 = (int)c.x; i3 = (int)c.y;
    } else {
        int4 iv = id32v[q];
        i0 = iv.x; i1 = iv.y; i2 = iv.z; i3 = iv.w;
    }
    atomicAdd(&s_sum[i0 & (NSEG - 1)], acc.x); atomicAdd(&s_cnt[i0 & (NSEG - 1)], 1);
    atomicAdd(&s_sum[i1 & (NSEG - 1)], acc.y); atomicAdd(&s_cnt[i1 & (NSEG - 1)], 1);
    atomicAdd(&s_sum[i2 & (NSEG - 1)], acc.z); atomicAdd(&s_cnt[i2 & (NSEG - 1)], 1);
    atomicAdd(&s_sum[i3 & (NSEG - 1)], acc.w); atomicAdd(&s_cnt[i3 & (NSEG - 1)], 1);

    // ---- W^2 phase ----
    const float4* __restrict__ Wb = (const float4*)(W + (size_t)b * NSEG * NSEG);
    float ws = 0.f;
    #pragma unroll
    for (int j = 0; j < 4; ++j) {
        float4 v = Wb[x * 2048 + j * 512 + tid];
        ws += v.x * v.x + v.y * v.y + v.z * v.z + v.w * v.w;
    }
    #pragma unroll
    for (int o = 16; o > 0; o >>= 1)
        ws += __shfl_xor_sync(0xffffffffu, ws, o);
    if ((tid & 31) == 0) red[tid >> 5] = ws;

    __syncthreads();

    // ---- flush ----
    for (int i = tid; i < NSEG; i += 512) {
        int c = s_cnt[i];
        if (c != 0) {
            atomicAdd(&g_msum[b * NSEG + i], s_sum[i]);
            atomicAdd(&g_mcnt[b * NSEG + i], (float)c);
        }
    }
    if (tid == 0) {
        double t = 0.0;
        #pragma unroll
        for (int w = 0; w < 16; ++w) t += (double)red[w];
        atomicAdd(&g_w2[b], t);
    }
}

// ---------------------------------------------------------------------------
// K3: quad[b] = m^T L m, element-parallel. 512 blocks x 256 thr.
// Block (b, x) covers rows [8x, 8x+8). Thread t owns column-group t (float4):
//   mreg = m4[t] (ONE shared read, reused for all 8 rows)
//   8 consecutive independent LDG.128 of L (MLP=8)
//   s = sum_k s_m[8x+k] * dot(Lk, mreg)
// No per-row shuffles. One block reduction -> g_quadp slot (no atomics).
// Last block reduces 512 partials, writes loss, resets all state.
// ---------------------------------------------------------------------------
__global__ __launch_bounds__(256) void k3(const float* __restrict__ L,
                                          float* __restrict__ out) {
    __shared__ float  s_m[NSEG];
    __shared__ double qred[8];
    __shared__ int    s_last;

    const int blk  = blockIdx.x;                     // 0..511
    const int b    = blk >> 7;                       // batch
    const int x    = blk & (QB - 1);                 // row-group
    const int tid  = threadIdx.x;
    const int warp = tid >> 5;
    const int lane = tid & 31;

    for (int i = tid; i < NSEG; i += 256) {
        float c = g_mcnt[b * NSEG + i];
        s_m[i] = (c > 0.f) ? g_msum[b * NSEG + i] / c : 0.f;
    }
    __syncthreads();

    const float4* __restrict__ Lf4 =
        (const float4*)(L + (size_t)b * NSEG * NSEG) + (size_t)x * 2048;

    // 8 independent, textually-consecutive global loads (front-batched)
    float4 v0 = Lf4[tid];
    float4 v1 = Lf4[tid + 256];
    float4 v2 = Lf4[tid + 512];
    float4 v3 = Lf4[tid + 768];
    float4 v4 = Lf4[tid + 1024];
    float4 v5 = Lf4[tid + 1280];
    float4 v6 = Lf4[tid + 1536];
    float4 v7 = Lf4[tid + 1792];

    // one 16B shared read, reused across all 8 rows
    const float4 mr = ((const float4*)s_m)[tid];
    const float* rowm = &s_m[x * 8];                 // 8 uniform scalars

    float s;
    s  = rowm[0] * (v0.x * mr.x + v0.y * mr.y + v0.z * mr.z + v0.w * mr.w);
    s += rowm[1] * (v1.x * mr.x + v1.y * mr.y + v1.z * mr.z + v1.w * mr.w);
    s += rowm[2] * (v2.x * mr.x + v2.y * mr.y + v2.z * mr.z + v2.w * mr.w);
    s += rowm[3] * (v3.x * mr.x + v3.y * mr.y + v3.z * mr.z + v3.w * mr.w);
    s += rowm[4] * (v4.x * mr.x + v4.y * mr.y + v4.z * mr.z + v4.w * mr.w);
    s += rowm[5] * (v5.x * mr.x + v5.y * mr.y + v5.z * mr.z + v5.w * mr.w);
    s += rowm[6] * (v6.x * mr.x + v6.y * mr.y + v6.z * mr.z + v6.w * mr.w);
    s += rowm[7] * (v7.x * mr.x + v7.y * mr.y + v7.z * mr.z + v7.w * mr.w);

    #pragma unroll
    for (int o = 16; o > 0; o >>= 1)
        s += __shfl_xor_sync(0xffffffffu, s, o);
    if (lane == 0) qred[warp] = (double)s;
    __syncthreads();

    if (tid == 0) {
        double t = 0.0;
        #pragma unroll
        for (int w = 0; w < 8; ++w) t += qred[w];
        g_quadp[blk] = t;                            // overwrite, no atomic

        __threadfence();
        unsigned int prev = atomicAdd(&g_done, 1u);
        s_last = (prev == K3_TOTAL - 1);
    }
    __syncthreads();

    if (s_last) {
        __threadfence();
        if (warp < NB) {                             // warps 0..3: one batch each
            double t = 0.0;
            #pragma unroll
            for (int j = 0; j < QB / 32; ++j)        // 4 loads
                t += g_quadp[warp * QB + j * 32 + lane];
            #pragma unroll
            for (int o = 16; o > 0; o >>= 1)
                t += __shfl_xor_sync(0xffffffffu, t, o);
            if (lane == 0) qred[warp] = t;
        }
        __syncthreads();
        if (tid == 0) {
            double loss = 0.0;
            #pragma unroll
            for (int k = 0; k < NB; ++k)
                loss += (2.0 / sqrt(g_w2[k])) * ((double)NCH * qred[k]);
            out[0] = (float)loss;
            __threadfence();
            #pragma unroll
            for (int k = 0; k < NB; ++k) g_w2[k] = 0.0;
            g_done = 0u;
        }
        // reset histogram accumulators for the next graph replay
        for (int i = tid; i < NB * NSEG; i += 256) {
            g_msum[i] = 0.f;
            g_mcnt[i] = 0.f;
        }
    }
}

extern "C" void kernel_launch(void* const* d_in, const int* in_sizes, int n_in,
                              void* d_out, int out_size) {
    const float* pred = (const float*)d_in[0];
    const float* W    = (const float*)d_in[1];
    const float* L    = (const float*)d_in[2];
    const void*  ids  = (const void*)d_in[3];
    float* out = (float*)d_out;

    k1<<<dim3(HB, NB), 512>>>(pred, ids, W);
    k3<<<K3_TOTAL, 256>>>(L, out);
}

// round 16
// speedup vs baseline: 1.1623x; 1.0415x over previous
#include <cuda_runtime.h>
#include <math.h>

#define NSEG 1024
#define NPIX (512 * 512)
#define NCH  21
#define NB   4
#define HB   128           // K1 x-blocks per batch (512 blocks total = 1 wave)
#define QB   128           // K3 blocks per batch -> 512 blocks
#define K3_TOTAL (QB * NB)

// Persistent state: starts zero (static init); K3's last block restores
// everything for the next graph replay.
__device__ float  g_msum[NB * NSEG];   // atomics in K1; zeroed by K3 last block
__device__ float  g_mcnt[NB * NSEG];   // atomics in K1; zeroed by K3 last block
__device__ double g_w2[NB];            // atomics in K1; zeroed by K3 last block
__device__ double g_quadp[K3_TOTAL];   // per-block partials — overwritten
__device__ unsigned int g_done;        // K3 counter; reset by K3 last block

// ---------------------------------------------------------------------------
// K1: grid (HB, NB) x 512 — one wave. Shared-mem histogram over 2048 px +
// 2048-float4 slice of ||W||^2. Flush via global atomics (skip empty bins).
// (Unchanged from R12 best — 67% DRAM.)
// ---------------------------------------------------------------------------
__global__ __launch_bounds__(512) void k1(const float* __restrict__ pred,
                                          const void* __restrict__ ids_v,
                                          const float* __restrict__ W) {
    __shared__ float s_sum[NSEG];
    __shared__ int   s_cnt[NSEG];
    __shared__ int   s_nonzero;
    __shared__ float red[16];

    const int tid = threadIdx.x;
    const int b   = blockIdx.y;
    const int x   = blockIdx.x;

    if (tid == 0) s_nonzero = 0;
    for (int i = tid; i < NSEG; i += 512) { s_sum[i] = 0.f; s_cnt[i] = 0; }
    __syncthreads();

    // dtype probe: int64 ids in [0,1024) -> all odd 32-bit words zero (L2-hot).
    if (tid < 128 && ((const unsigned int*)ids_v)[2 * tid + 1] != 0u)
        atomicOr(&s_nonzero, 1);
    __syncthreads();
    const int is64 = !s_nonzero;

    // ---- histogram phase ----
    const float4* __restrict__ p4 =
        (const float4*)(pred + (size_t)b * NCH * NPIX);
    const int4* __restrict__ id32v =
        (const int4*)((const int*)ids_v + (size_t)b * NPIX);
    const longlong2* __restrict__ id64v =
        (const longlong2*)((const long long*)ids_v + (size_t)b * NPIX);

    const int q = x * 512 + tid;                     // one float4-group/thread
    float4 acc = make_float4(0.f, 0.f, 0.f, 0.f);
    #pragma unroll
    for (int c = 0; c < NCH; ++c) {
        float4 v = p4[(size_t)c * (NPIX / 4) + q];
        acc.x += v.x; acc.y += v.y; acc.z += v.z; acc.w += v.w;
    }
    int i0, i1, i2, i3;
    if (is64) {
        longlong2 a = id64v[2 * q];
        longlong2 c = id64v[2 * q + 1];
        i0 = (int)a.x; i1 = (int)a.y; i2 = (int)c.x; i3 = (int)c.y;
    } else {
        int4 iv = id32v[q];
        i0 = iv.x; i1 = iv.y; i2 = iv.z; i3 = iv.w;
    }
    atomicAdd(&s_sum[i0 & (NSEG - 1)], acc.x); atomicAdd(&s_cnt[i0 & (NSEG - 1)], 1);
    atomicAdd(&s_sum[i1 & (NSEG - 1)], acc.y); atomicAdd(&s_cnt[i1 & (NSEG - 1)], 1);
    atomicAdd(&s_sum[i2 & (NSEG - 1)], acc.z); atomicAdd(&s_cnt[i2 & (NSEG - 1)], 1);
    atomicAdd(&s_sum[i3 & (NSEG - 1)], acc.w); atomicAdd(&s_cnt[i3 & (NSEG - 1)], 1);

    // ---- W^2 phase ----
    const float4* __restrict__ Wb = (const float4*)(W + (size_t)b * NSEG * NSEG);
    float ws = 0.f;
    #pragma unroll
    for (int j = 0; j < 4; ++j) {
        float4 v = Wb[x * 2048 + j * 512 + tid];
        ws += v.x * v.x + v.y * v.y + v.z * v.z + v.w * v.w;
    }
    #pragma unroll
    for (int o = 16; o > 0; o >>= 1)
        ws += __shfl_xor_sync(0xffffffffu, ws, o);
    if ((tid & 31) == 0) red[tid >> 5] = ws;

    __syncthreads();

    // ---- flush ----
    for (int i = tid; i < NSEG; i += 512) {
        int c = s_cnt[i];
        if (c != 0) {
            atomicAdd(&g_msum[b * NSEG + i], s_sum[i]);
            atomicAdd(&g_mcnt[b * NSEG + i], (float)c);
        }
    }
    if (tid == 0) {
        double t = 0.0;
        #pragma unroll
        for (int w = 0; w < 16; ++w) t += (double)red[w];
        atomicAdd(&g_w2[b], t);
    }
}

// ---------------------------------------------------------------------------
// K3: quad[b] = m^T L m via cp.async tile staging.
// 512 blocks x 256 thr. Block (b,x) owns rows [8x, 8x+8) = 32KB of L.
//   1) issue 8 cp.async.cg (16B) per thread -> s_L   (all in flight at once,
//      no register scoreboard serialization possible)
//   2) overlap: m preamble (read msum/mcnt, divide) while copies fly
//   3) wait_group 0; compute 8 dots from shared; block-reduce -> slot
// Last block reduces 512 partials, writes loss, resets all state.
// ---------------------------------------------------------------------------
__global__ __launch_bounds__(256) void k3(const float* __restrict__ L,
                                          float* __restrict__ out) {
    __shared__ float4 s_L[2048];        // 32 KB tile
    __shared__ float  s_m[NSEG];        // 4 KB
    __shared__ double qred[8];
    __shared__ int    s_last;

    const int blk  = blockIdx.x;                     // 0..511
    const int b    = blk >> 7;                       // batch
    const int x    = blk & (QB - 1);                 // row-group
    const int tid  = threadIdx.x;
    const int warp = tid >> 5;
    const int lane = tid & 31;

    // ---- 1) kick off the L-tile copy (8 x 16B per thread) ----
    const float4* __restrict__ Lf4 =
        (const float4*)(L + (size_t)b * NSEG * NSEG) + (size_t)x * 2048 + tid;
    unsigned int sdst =
        (unsigned int)__cvta_generic_to_shared(&s_L[tid]);
    #pragma unroll
    for (int k = 0; k < 8; ++k) {
        asm volatile("cp.async.cg.shared.global [%0], [%1], 16;"
                     :: "r"(sdst + k * 256 * 16), "l"(Lf4 + k * 256));
    }
    asm volatile("cp.async.commit_group;");

    // ---- 2) m preamble overlapped with the async copies ----
    for (int i = tid; i < NSEG; i += 256) {
        float c = g_mcnt[b * NSEG + i];
        s_m[i] = (c > 0.f) ? g_msum[b * NSEG + i] / c : 0.f;
    }

    asm volatile("cp.async.wait_group 0;");
    __syncthreads();

    // ---- 3) compute: thread t owns column-group t across 8 rows ----
    const float4 mr = ((const float4*)s_m)[tid];     // one 16B read, reused x8
    float r0 = s_m[x * 8 + 0], r1 = s_m[x * 8 + 1];
    float r2 = s_m[x * 8 + 2], r3 = s_m[x * 8 + 3];
    float r4 = s_m[x * 8 + 4], r5 = s_m[x * 8 + 5];
    float r6 = s_m[x * 8 + 6], r7 = s_m[x * 8 + 7];

    float4 v;
    float s;
    v = s_L[tid];          s  = r0 * (v.x*mr.x + v.y*mr.y + v.z*mr.z + v.w*mr.w);
    v = s_L[tid + 256];    s += r1 * (v.x*mr.x + v.y*mr.y + v.z*mr.z + v.w*mr.w);
    v = s_L[tid + 512];    s += r2 * (v.x*mr.x + v.y*mr.y + v.z*mr.z + v.w*mr.w);
    v = s_L[tid + 768];    s += r3 * (v.x*mr.x + v.y*mr.y + v.z*mr.z + v.w*mr.w);
    v = s_L[tid + 1024];   s += r4 * (v.x*mr.x + v.y*mr.y + v.z*mr.z + v.w*mr.w);
    v = s_L[tid + 1280];   s += r5 * (v.x*mr.x + v.y*mr.y + v.z*mr.z + v.w*mr.w);
    v = s_L[tid + 1536];   s += r6 * (v.x*mr.x + v.y*mr.y + v.z*mr.z + v.w*mr.w);
    v = s_L[tid + 1792];   s += r7 * (v.x*mr.x + v.y*mr.y + v.z*mr.z + v.w*mr.w);

    #pragma unroll
    for (int o = 16; o > 0; o >>= 1)
        s += __shfl_xor_sync(0xffffffffu, s, o);
    if (lane == 0) qred[warp] = (double)s;
    __syncthreads();

    if (tid == 0) {
        double t = 0.0;
        #pragma unroll
        for (int w = 0; w < 8; ++w) t += qred[w];
        g_quadp[blk] = t;                            // overwrite, no atomic

        __threadfence();
        unsigned int prev = atomicAdd(&g_done, 1u);
        s_last = (prev == K3_TOTAL - 1);
    }
    __syncthreads();

    if (s_last) {
        __threadfence();
        if (warp < NB) {                             // warps 0..3: one batch each
            double t = 0.0;
            #pragma unroll
            for (int j = 0; j < QB / 32; ++j)        // 4 loads
                t += g_quadp[warp * QB + j * 32 + lane];
            #pragma unroll
            for (int o = 16; o > 0; o >>= 1)
                t += __shfl_xor_sync(0xffffffffu, t, o);
            if (lane == 0) qred[warp] = t;
        }
        __syncthreads();
        if (tid == 0) {
            double loss = 0.0;
            #pragma unroll
            for (int k = 0; k < NB; ++k)
                loss += (2.0 / sqrt(g_w2[k])) * ((double)NCH * qred[k]);
            out[0] = (float)loss;
            __threadfence();
            #pragma unroll
            for (int k = 0; k < NB; ++k) g_w2[k] = 0.0;
            g_done = 0u;
        }
        // reset histogram accumulators for the next graph replay
        for (int i = tid; i < NB * NSEG; i += 256) {
            g_msum[i] = 0.f;
            g_mcnt[i] = 0.f;
        }
    }
}

extern "C" void kernel_launch(void* const* d_in, const int* in_sizes, int n_in,
                              void* d_out, int out_size) {
    const float* pred = (const float*)d_in[0];
    const float* W    = (const float*)d_in[1];
    const float* L    = (const float*)d_in[2];
    const void*  ids  = (const void*)d_in[3];
    float* out = (float*)d_out;

    k1<<<dim3(HB, NB), 512>>>(pred, ids, W);
    k3<<<K3_TOTAL, 256>>>(L, out);
}